// round 1
// baseline (speedup 1.0000x reference)
#include <cuda_runtime.h>

// ---------------------------------------------------------------------------
// Mipmapped texture sampling, GB300.
// Pyramid layout: HWC (16 channels contiguous = 64B per texel), fp32.
// Level i (i>=1) texel = 0.25 * 2x2 of base at y0 = y*2^i + 2^(i-1) - 1
// (exact algebra of align_corners=False bilinear resize by power of two).
// ---------------------------------------------------------------------------

#define CH 16
#define NLEV 8

// total floats: 16 * (512^2+256^2+128^2+64^2+32^2+16^2+8^2+4^2) = 5,592,320
__device__ __align__(16) float g_pyr[5592320];

__constant__ int c_off[NLEV] = {
    0, 4194304, 5242880, 5505024, 5570560, 5586944, 5591040, 5592064
};

// ---------------------------------------------------------------------------
// Kernel 1: CHW (16,512,512) -> HWC level 0
// Each thread writes one float4 (4 channels) of one pixel.
// ---------------------------------------------------------------------------
__global__ void k_transpose(const float* __restrict__ tex) {
    int idx = blockIdx.x * blockDim.x + threadIdx.x;   // 512*512*4 threads
    if (idx >= 512 * 512 * 4) return;
    int t   = idx & 3;          // which channel quartet
    int pix = idx >> 2;         // y*512 + x
    const int plane = 512 * 512;
    float4 v;
    v.x = __ldg(&tex[(4 * t + 0) * plane + pix]);
    v.y = __ldg(&tex[(4 * t + 1) * plane + pix]);
    v.z = __ldg(&tex[(4 * t + 2) * plane + pix]);
    v.w = __ldg(&tex[(4 * t + 3) * plane + pix]);
    reinterpret_cast<float4*>(g_pyr)[pix * 4 + t] = v;
}

// ---------------------------------------------------------------------------
// Kernel 2: build levels 1..7 directly from level 0 (2x2 average).
// 87,376 pixels total * 4 channel-quartets = 349,504 threads.
// ---------------------------------------------------------------------------
__global__ void k_mips() {
    int idx = blockIdx.x * blockDim.x + threadIdx.x;
    if (idx >= 349504) return;
    int t   = idx & 3;
    int rem = idx >> 2;

    int l = 1;
#pragma unroll
    for (int i = 1; i < NLEV; i++) {
        int s  = 512 >> i;
        int np = s * s;
        if (rem < np) { l = i; break; }
        rem -= np;
    }
    int s  = 512 >> l;
    int x  = rem & (s - 1);
    int y  = rem >> (9 - l);
    int sc = 1 << l;
    int x0 = x * sc + (sc >> 1) - 1;
    int y0 = y * sc + (sc >> 1) - 1;

    const float4* b0 = reinterpret_cast<const float4*>(g_pyr);
    float4 a = __ldg(&b0[(y0       * 512 + x0    ) * 4 + t]);
    float4 b = __ldg(&b0[(y0       * 512 + x0 + 1) * 4 + t]);
    float4 c = __ldg(&b0[((y0 + 1) * 512 + x0    ) * 4 + t]);
    float4 d = __ldg(&b0[((y0 + 1) * 512 + x0 + 1) * 4 + t]);

    float4 r;
    r.x = 0.25f * (a.x + b.x + c.x + d.x);
    r.y = 0.25f * (a.y + b.y + c.y + d.y);
    r.z = 0.25f * (a.z + b.z + c.z + d.z);
    r.w = 0.25f * (a.w + b.w + c.w + d.w);
    reinterpret_cast<float4*>(g_pyr + c_off[l])[(y * s + x) * 4 + t] = r;
}

// ---------------------------------------------------------------------------
// Kernel 3: sample. 4 threads per query, each owns 4 channels.
// ---------------------------------------------------------------------------
__device__ __forceinline__ float4 sample_level(int l, float gx, float gy, int t) {
    int   s  = 512 >> l;
    float fs = (float)(s - 1);
    float x = fminf(fmaxf((gx + 1.0f) * 0.5f * fs, 0.0f), fs);
    float y = fminf(fmaxf((gy + 1.0f) * 0.5f * fs, 0.0f), fs);
    int x0 = (int)x;                 // x >= 0 -> trunc == floor; x <= fs -> x0 <= s-1
    int y0 = (int)y;
    int x1 = min(x0 + 1, s - 1);
    int y1 = min(y0 + 1, s - 1);
    float fx = x - (float)x0;
    float fy = y - (float)y0;

    const float4* b = reinterpret_cast<const float4*>(g_pyr + c_off[l]);
    int r0 = y0 * s, r1 = y1 * s;
    float4 v00 = __ldg(&b[(r0 + x0) * 4 + t]);
    float4 v01 = __ldg(&b[(r0 + x1) * 4 + t]);
    float4 v10 = __ldg(&b[(r1 + x0) * 4 + t]);
    float4 v11 = __ldg(&b[(r1 + x1) * 4 + t]);

    float w00 = (1.0f - fx) * (1.0f - fy);
    float w01 = fx * (1.0f - fy);
    float w10 = (1.0f - fx) * fy;
    float w11 = fx * fy;

    float4 r;
    r.x = v00.x * w00 + v01.x * w01 + v10.x * w10 + v11.x * w11;
    r.y = v00.y * w00 + v01.y * w01 + v10.y * w10 + v11.y * w11;
    r.z = v00.z * w00 + v01.z * w01 + v10.z * w10 + v11.z * w11;
    r.w = v00.w * w00 + v01.w * w01 + v10.w * w10 + v11.w * w11;
    return r;
}

__global__ void k_sample(const float* __restrict__ uv,
                         const float* __restrict__ p,
                         float* __restrict__ out, int N) {
    int idx = blockIdx.x * blockDim.x + threadIdx.x;
    int q = idx >> 2;
    if (q >= N) return;
    int t = idx & 3;

    float u  = __ldg(&uv[2 * q]);
    float v  = __ldg(&uv[2 * q + 1]);
    float pp = __ldg(&p[q]);

    float lf = pp * (float)(NLEV - 1);
    int   l0 = (int)floorf(lf);
    l0 = max(0, min(l0, NLEV - 1));
    int   l1 = min(l0 + 1, NLEV - 1);
    float alpha = lf - (float)l0;

    float gx = 2.0f * u - 1.0f;
    float gy = 2.0f * v - 1.0f;

    float4 s0 = sample_level(l0, gx, gy, t);
    float4 s1 = sample_level(l1, gx, gy, t);

    float ia = 1.0f - alpha;
    float4 r;
    r.x = s0.x * ia + s1.x * alpha;
    r.y = s0.y * ia + s1.y * alpha;
    r.z = s0.z * ia + s1.z * alpha;
    r.w = s0.w * ia + s1.w * alpha;

    // streaming store: don't let the 64MB output stream evict the pyramid from L2
    __stcs(reinterpret_cast<float4*>(out) + q * 4 + t, r);
}

// ---------------------------------------------------------------------------
extern "C" void kernel_launch(void* const* d_in, const int* in_sizes, int n_in,
                              void* d_out, int out_size) {
    const float* uv  = (const float*)d_in[0];
    const float* p   = (const float*)d_in[1];
    const float* tex = (const float*)d_in[2];
    float* out = (float*)d_out;
    int N = in_sizes[1];          // number of queries (p element count)

    k_transpose<<<(512 * 512 * 4) / 256, 256>>>(tex);
    k_mips<<<(349504 + 255) / 256, 256>>>();
    int total = N * 4;
    k_sample<<<(total + 255) / 256, 256>>>(uv, p, out, N);
}